// round 13
// baseline (speedup 1.0000x reference)
#include <cuda_runtime.h>
#include <cuda_bf16.h>
#include <cstdint>

#define E 1024
#define R 16
#define BATCH 4
#define S 2048
#define BS (BATCH * S)

static const long long EE  = (long long)E * E;
static const long long BSE = (long long)BATCH * S * E;   // 8388608
static const long long SE  = (long long)S * E;
static const long long SS  = (long long)S * S;

// ---------------- device scratch ----------------
// Every GEMM operand lives as bf16 hi/lo planes (split once, consumed many times).
__device__ __nv_bfloat16 g_inX[(size_t)3 * 2 * BATCH * S * E];   // q/k/v hi+lo
__device__ __nv_bfloat16 g_Weff_s[(size_t)3 * 2 * E * E];        // Weff hi+lo
__device__ __nv_bfloat16 g_QK[(size_t)2 * 2 * BATCH * S * E];    // Q,K hi+lo
__device__ float         g_V[(size_t)BATCH * S * E];             // V fp32 (pre-transpose)
__device__ __nv_bfloat16 g_Vt_s[(size_t)2 * BATCH * S * E];      // V^T hi+lo ([b][e][s])
__device__ __nv_bfloat16 g_P[(size_t)2 * BATCH * S * S];         // scores->probs hi+lo
__device__ __nv_bfloat16 g_AO[(size_t)2 * BATCH * S * E];        // attn out hi+lo
__device__ __nv_bfloat16 g_Ow_s[(size_t)2 * E * E];              // O weight hi+lo

#define SELB_INX  0
#define SELB_WEFF 1
#define SELB_QK   2
#define SELB_VT   3
#define SELB_P    4
#define SELB_AO   5
#define SELB_OW   6

__device__ __forceinline__ const __nv_bfloat16* resolve_bf(int sel) {
    switch (sel) {
        case SELB_INX:  return g_inX;
        case SELB_WEFF: return g_Weff_s;
        case SELB_QK:   return g_QK;
        case SELB_VT:   return g_Vt_s;
        case SELB_P:    return g_P;
        case SELB_AO:   return g_AO;
        default:        return g_Ow_s;
    }
}

// ---------------- bf16 helpers ----------------
__device__ __forceinline__ uint32_t bf16x2_rn(float x0, float x1) {
    uint32_t r;
    asm("cvt.rn.bf16x2.f32 %0, %1, %2;" : "=r"(r) : "f"(x1), "f"(x0));
    return r;
}
__device__ __forceinline__ float bf_lo_f(uint32_t w) { return __uint_as_float(w << 16); }
__device__ __forceinline__ float bf_hi_f(uint32_t w) { return __uint_as_float(w & 0xffff0000u); }

__device__ __forceinline__ void mma_bf16(float* c, const uint32_t* a, const uint32_t* b) {
    asm volatile("mma.sync.aligned.m16n8k16.row.col.f32.bf16.bf16.f32 "
        "{%0,%1,%2,%3}, {%4,%5,%6,%7}, {%8,%9}, {%0,%1,%2,%3};"
        : "+f"(c[0]), "+f"(c[1]), "+f"(c[2]), "+f"(c[3])
        : "r"(a[0]), "r"(a[1]), "r"(a[2]), "r"(a[3]), "r"(b[0]), "r"(b[1]));
}

// split one fp32 into (hi,lo) bf16 pair words for two adjacent values
__device__ __forceinline__ void split2(float x0, float x1, uint32_t& hw, uint32_t& lw) {
    hw = bf16x2_rn(x0, x1);
    lw = bf16x2_rn(x0 - bf_lo_f(hw), x1 - bf_hi_f(hw));
}

// ---------------- input pre-split: q/k/v -> g_inX, Ow -> g_Ow_s ----------------
__global__ __launch_bounds__(256) void split_inputs_kernel(
    const float* __restrict__ q, const float* __restrict__ k,
    const float* __restrict__ v, const float* __restrict__ ow)
{
    const int z = blockIdx.z;
    const long long n = (z < 3) ? BSE : EE;           // elements
    const long long i4 = (long long)blockIdx.x * 256 + threadIdx.x;  // float4 index
    if (i4 * 4 >= n) return;
    const float* src = (z == 0) ? q : (z == 1) ? k : (z == 2) ? v : ow;
    __nv_bfloat16* hi = (z < 3) ? (g_inX + (long long)z * 2 * BSE) : g_Ow_s;
    __nv_bfloat16* lo = hi + ((z < 3) ? BSE : EE);
    const float4 x = reinterpret_cast<const float4*>(src)[i4];
    uint32_t h0, l0, h1, l1;
    split2(x.x, x.y, h0, l0);
    split2(x.z, x.w, h1, l1);
    reinterpret_cast<uint32_t*>(hi)[i4 * 2]     = h0;
    reinterpret_cast<uint32_t*>(hi)[i4 * 2 + 1] = h1;
    reinterpret_cast<uint32_t*>(lo)[i4 * 2]     = l0;
    reinterpret_cast<uint32_t*>(lo)[i4 * 2 + 1] = l1;
}

// ---------------- W_eff = W + B @ A, split to hi/lo ----------------
__global__ __launch_bounds__(256) void weff_kernel(
    const float* __restrict__ Wq, const float* __restrict__ Wk, const float* __restrict__ Wv,
    const float* __restrict__ Aq, const float* __restrict__ Bq,
    const float* __restrict__ Ak, const float* __restrict__ Bk,
    const float* __restrict__ Av, const float* __restrict__ Bv)
{
    const int z = blockIdx.z;
    const float* W  = (z == 0) ? Wq : (z == 1) ? Wk : Wv;
    const float* Am = (z == 0) ? Aq : (z == 1) ? Ak : Av;
    const float* Bm = (z == 0) ? Bq : (z == 1) ? Bk : Bv;
    const int idx2 = blockIdx.x * 256 + threadIdx.x;   // pair index
    const int f = (idx2 * 2) >> 10;
    const int e = (idx2 * 2) & 1023;
    float s0 = W[idx2 * 2], s1 = W[idx2 * 2 + 1];
#pragma unroll
    for (int r = 0; r < R; r++) {
        const float b = Bm[f * R + r];
        s0 += b * Am[r * E + e];
        s1 += b * Am[r * E + e + 1];
    }
    uint32_t hw, lw;
    split2(s0, s1, hw, lw);
    __nv_bfloat16* hi = g_Weff_s + (long long)z * 2 * EE;
    reinterpret_cast<uint32_t*>(hi)[idx2] = hw;
    reinterpret_cast<uint32_t*>(hi + EE)[idx2] = lw;
}

// ---------------- V transpose + split: g_V[b][s][e] -> g_Vt_s[b][e][s] hi/lo ----
__global__ __launch_bounds__(256) void transpose_v_kernel()
{
    __shared__ float t[32][33];
    const int b = blockIdx.z;
    const int s0 = blockIdx.x * 32;
    const int e0 = blockIdx.y * 32;
    const int tx = threadIdx.x & 31;
    const int ty = threadIdx.x >> 5;   // 0..7
    const float* V = g_V + (long long)b * SE;
    __nv_bfloat16* Vh = g_Vt_s + (long long)b * SE;
    __nv_bfloat16* Vl = Vh + BSE;
#pragma unroll
    for (int r = 0; r < 4; r++)
        t[ty + r * 8][tx] = V[(long long)(s0 + ty + r * 8) * E + e0 + tx];
    __syncthreads();
#pragma unroll
    for (int r = 0; r < 4; r++) {
        const float x = t[tx][ty + r * 8];
        const __nv_bfloat16 h = __float2bfloat16(x);
        const __nv_bfloat16 l = __float2bfloat16(x - __bfloat162float(h));
        const long long o = (long long)(e0 + ty + r * 8) * S + s0 + tx;
        Vh[o] = h;
        Vl[o] = l;
    }
}

// ---------------- split-BF16 3-term HMMA GEMM, pre-split operands ----------------
// C = alpha * A @ B^T; A,B given as bf16 hi/lo planes (split hoisted out of the
// loop). acc += Ah*Bh + Al*Bh + Ah*Bl (Al*Bl dropped, ~2^-16 rel).
// CTA 128x128x32, 8 warps (2x4), warp tile 64x32, 2 CTAs/SM (R9-proven config).
// Producer per half: 4 LDG.128 (bf16) + 16 STS.32, NO conversions.
// Smem word layout per buffer (8192 words), proven since R7:
//  A hi 0..2047, A lo 2048..4095   (fb = (m>>4)*2 + kc, 128-word frag blocks)
//  B hi 4096..6143, B lo 6144..8191 (fb = (n>>3)*2 + kc, 64-word frag blocks)
// emode: 0 = fp32 to extC; 1 = hi/lo planes to resolve_bf(selC);
//        2 = QKV special (z<2 -> g_QK hi/lo, z==2 -> g_V fp32)
#define GEMM_SMEM_BYTES (2 * 8192 * 4)
#define NTHREADS 256

__global__ __launch_bounds__(NTHREADS, 2) void gemm_hmma(
    int selA, long long offA, long long planeA, int ldA, long long sA,
    int selB, long long offB, long long planeB, int ldB, long long sB,
    float* extC, int selC, long long offC, long long planeC, int ldC, long long sC,
    int emode, int K, float alpha)
{
    extern __shared__ uint32_t smw[];
    const int tid = threadIdx.x;
    const int wid = tid >> 5, lane = tid & 31;
    const int g = lane >> 2, t4 = lane & 3;
    const int warp_m = wid & 1, warp_n = wid >> 1;   // 2x4 warps, 64x32 warp tile
    const int z = blockIdx.z;

    const __nv_bfloat16* Ahi = resolve_bf(selA) + offA + (long long)z * sA
                               + (long long)blockIdx.y * 128 * ldA;
    const __nv_bfloat16* Bhi = resolve_bf(selB) + offB + (long long)z * sB
                               + (long long)blockIdx.x * 128 * ldB;

    float acc[4][4][4];
#pragma unroll
    for (int i = 0; i < 4; i++)
#pragma unroll
        for (int j = 0; j < 4; j++)
#pragma unroll
            for (int q = 0; q < 4; q++) acc[i][j][q] = 0.f;

    uint4 v[4];   // producer: 4 uint4 (8 bf16 each) live per half

    // slots 0..2047: region = slot>>9 (0 A-hi, 1 A-lo, 2 B-hi, 3 B-lo);
    // r = slot&511: m = r>>2, q8 = r&3 (8-k chunk within the 32-k step).
    auto ldg_half = [&](int step, int h) {
#pragma unroll
        for (int j = 0; j < 4; j++) {
            const int slot = tid + (4 * h + j) * NTHREADS;
            const int region = slot >> 9;
            const int r = slot & 511;
            const int m = r >> 2, q8 = r & 3;
            const __nv_bfloat16* src =
                (region < 2) ? (Ahi + (region == 1 ? planeA : 0))
                             : (Bhi + (region == 3 ? planeB : 0));
            const int ld = (region < 2) ? ldA : ldB;
            v[j] = *reinterpret_cast<const uint4*>(src + (long long)m * ld + step * 32 + q8 * 8);
        }
    };

    auto sts_half = [&](int s, int h) {
        uint32_t* base = smw + s * 8192;
#pragma unroll
        for (int j = 0; j < 4; j++) {
            const int slot = tid + (4 * h + j) * NTHREADS;
            const int region = slot >> 9;
            const int r = slot & 511;
            const int m = r >> 2, q8 = r & 3;
            const int kc = q8 >> 1, khalf = q8 & 1;
            const uint32_t w4[4] = { v[j].x, v[j].y, v[j].z, v[j].w };
            if (region < 2) {
                const int fb = (m >> 4) * 2 + kc;
                const int reg = ((m >> 3) & 1) + 2 * khalf;
                const int off = (region == 1) ? 2048 : 0;
#pragma unroll
                for (int w = 0; w < 2; w++) {   // unrolled x4 below via pairs
                    base[off + fb * 128 + ((m & 7) * 4 + 2 * w + 0) * 4 + reg] = w4[2 * w + 0];
                    base[off + fb * 128 + ((m & 7) * 4 + 2 * w + 1) * 4 + reg] = w4[2 * w + 1];
                }
            } else {
                const int fb = (m >> 3) * 2 + kc;
                const int off = 4096 + ((region == 3) ? 2048 : 0);
#pragma unroll
                for (int w = 0; w < 2; w++) {
                    base[off + fb * 64 + ((m & 7) * 4 + 2 * w + 0) * 2 + khalf] = w4[2 * w + 0];
                    base[off + fb * 64 + ((m & 7) * 4 + 2 * w + 1) * 2 + khalf] = w4[2 * w + 1];
                }
            }
        }
    };

    auto compute_kc = [&](int s, int kc) {
        const uint32_t* base = smw + s * 8192;
        uint32_t aF[2][4][4];
#pragma unroll
        for (int mt = 0; mt < 4; mt++) {
            const int fb = (warp_m * 4 + mt) * 2 + kc;
            const uint4 h = *reinterpret_cast<const uint4*>(base + fb * 128 + lane * 4);
            const uint4 l = *reinterpret_cast<const uint4*>(base + 2048 + fb * 128 + lane * 4);
            aF[0][mt][0] = h.x; aF[0][mt][1] = h.y; aF[0][mt][2] = h.z; aF[0][mt][3] = h.w;
            aF[1][mt][0] = l.x; aF[1][mt][1] = l.y; aF[1][mt][2] = l.z; aF[1][mt][3] = l.w;
        }
#pragma unroll
        for (int nh = 0; nh < 2; nh++) {
            uint32_t bF[2][2][2];
#pragma unroll
            for (int nt = 0; nt < 2; nt++) {
                const int fb = (warp_n * 4 + nh * 2 + nt) * 2 + kc;
                const uint2 h = *reinterpret_cast<const uint2*>(base + 4096 + fb * 64 + lane * 2);
                const uint2 l = *reinterpret_cast<const uint2*>(base + 6144 + fb * 64 + lane * 2);
                bF[0][nt][0] = h.x; bF[0][nt][1] = h.y;
                bF[1][nt][0] = l.x; bF[1][nt][1] = l.y;
            }
#pragma unroll
            for (int mt = 0; mt < 4; mt++)
#pragma unroll
                for (int nt = 0; nt < 2; nt++)
                    mma_bf16(acc[mt][nh * 2 + nt], aF[0][mt], bF[0][nt]);
#pragma unroll
            for (int mt = 0; mt < 4; mt++)
#pragma unroll
                for (int nt = 0; nt < 2; nt++)
                    mma_bf16(acc[mt][nh * 2 + nt], aF[1][mt], bF[0][nt]);
#pragma unroll
            for (int mt = 0; mt < 4; mt++)
#pragma unroll
                for (int nt = 0; nt < 2; nt++)
                    mma_bf16(acc[mt][nh * 2 + nt], aF[0][mt], bF[1][nt]);
        }
    };

    const int nsteps = K / 32;
    ldg_half(0, 0); sts_half(0, 0);
    ldg_half(0, 1); sts_half(0, 1);
    __syncthreads();

    for (int step = 0; step < nsteps; step++) {
        const int s = step & 1;
        const bool more = (step + 1 < nsteps);
        if (more) ldg_half(step + 1, 0);
        compute_kc(s, 0);
        if (more) { sts_half(1 - s, 0); ldg_half(step + 1, 1); }
        compute_kc(s, 1);
        if (more) sts_half(1 - s, 1);
        __syncthreads();
    }

    // ---- epilogue ----
    const bool f32path = (emode == 0) || (emode == 2 && z == 2);
    float* Cf = nullptr;
    __nv_bfloat16* Dh = nullptr;
    long long planeD = planeC;
    if (emode == 0) Cf = extC + (long long)z * sC;
    else if (emode == 2 && z == 2) { Cf = g_V; }
    else if (emode == 2) { Dh = g_QK + (long long)z * 2 * BSE; planeD = BSE; }
    else Dh = const_cast<__nv_bfloat16*>(resolve_bf(selC)) + offC + (long long)z * sC;

#pragma unroll
    for (int mt = 0; mt < 4; mt++) {
        const long long row = (long long)blockIdx.y * 128 + warp_m * 64 + mt * 16 + g;
        const long long col0 = (long long)blockIdx.x * 128 + warp_n * 32;
#pragma unroll
        for (int nt = 0; nt < 4; nt++) {
            const long long col = col0 + nt * 8 + t4 * 2;
            const float x0 = acc[mt][nt][0] * alpha, x1 = acc[mt][nt][1] * alpha;
            const float y0 = acc[mt][nt][2] * alpha, y1 = acc[mt][nt][3] * alpha;
            if (f32path) {
                *reinterpret_cast<float2*>(Cf + row * ldC + col) = make_float2(x0, x1);
                *reinterpret_cast<float2*>(Cf + (row + 8) * ldC + col) = make_float2(y0, y1);
            } else {
                uint32_t hw, lw;
                split2(x0, x1, hw, lw);
                *reinterpret_cast<uint32_t*>(Dh + row * ldC + col) = hw;
                *reinterpret_cast<uint32_t*>(Dh + planeD + row * ldC + col) = lw;
                split2(y0, y1, hw, lw);
                *reinterpret_cast<uint32_t*>(Dh + (row + 8) * ldC + col) = hw;
                *reinterpret_cast<uint32_t*>(Dh + planeD + (row + 8) * ldC + col) = lw;
            }
        }
    }
}

// ---------------- row softmax over S=2048 on hi/lo planes (in place) ----------------
__global__ __launch_bounds__(256) void softmax_kernel()
{
    const long long row = blockIdx.x;
    __nv_bfloat16* ph = g_P + row * (long long)S;
    __nv_bfloat16* pl = ph + (long long)BATCH * SS;
    const int t = threadIdx.x;

    float v[8];
    float m = -1e30f;
#pragma unroll
    for (int i = 0; i < 8; i++) {
        const int c = t + i * 256;
        v[i] = __bfloat162float(ph[c]) + __bfloat162float(pl[c]);
        m = fmaxf(m, v[i]);
    }
    __shared__ float red[8];
#pragma unroll
    for (int o = 16; o; o >>= 1) m = fmaxf(m, __shfl_xor_sync(0xffffffffu, m, o));
    if ((t & 31) == 0) red[t >> 5] = m;
    __syncthreads();
    float mx = red[0];
#pragma unroll
    for (int w = 1; w < 8; w++) mx = fmaxf(mx, red[w]);

    float s = 0.f;
#pragma unroll
    for (int i = 0; i < 8; i++) {
        v[i] = __expf(v[i] - mx);
        s += v[i];
    }
#pragma unroll
    for (int o = 16; o; o >>= 1) s += __shfl_xor_sync(0xffffffffu, s, o);
    __syncthreads();
    if ((t & 31) == 0) red[t >> 5] = s;
    __syncthreads();
    float tot = 0.f;
#pragma unroll
    for (int w = 0; w < 8; w++) tot += red[w];
    const float inv = 1.0f / tot;
#pragma unroll
    for (int i = 0; i < 8; i++) {
        const int c = t + i * 256;
        const float p = v[i] * inv;
        const __nv_bfloat16 h = __float2bfloat16(p);
        ph[c] = h;
        pl[c] = __float2bfloat16(p - __bfloat162float(h));
    }
}

// ---------------- launch ----------------
extern "C" void kernel_launch(void* const* d_in, const int* in_sizes, int n_in,
                              void* d_out, int out_size)
{
    (void)in_sizes; (void)n_in; (void)out_size;
    const float* query = (const float*)d_in[0];
    const float* key   = (const float*)d_in[1];
    const float* value = (const float*)d_in[2];
    const float* Qw    = (const float*)d_in[3];
    const float* Kw    = (const float*)d_in[4];
    const float* Vw    = (const float*)d_in[5];
    const float* Qa    = (const float*)d_in[6];
    const float* Qb    = (const float*)d_in[7];
    const float* Ka    = (const float*)d_in[8];
    const float* Kb    = (const float*)d_in[9];
    const float* Va    = (const float*)d_in[10];
    const float* Vb    = (const float*)d_in[11];
    const float* Ow    = (const float*)d_in[12];
    float* out = (float*)d_out;

    static bool attr_done = false;
    if (!attr_done) {
        cudaFuncSetAttribute(gemm_hmma, cudaFuncAttributeMaxDynamicSharedMemorySize,
                             GEMM_SMEM_BYTES);
        attr_done = true;
    }

    // 1. split inputs (q/k/v + Ow) into bf16 hi/lo planes
    split_inputs_kernel<<<dim3((int)(BSE / 4 / 256), 1, 4), 256>>>(query, key, value, Ow);

    // 2. fold LoRA into weights, split to hi/lo
    weff_kernel<<<dim3(E * E / 2 / 256, 1, 3), 256>>>(Qw, Kw, Vw, Qa, Qb, Ka, Kb, Va, Vb);

    // 3. Q/K/V projections (merged, z=3): C -> Q,K hi/lo planes; V fp32
    gemm_hmma<<<dim3(E / 128, BS / 128, 3), NTHREADS, GEMM_SMEM_BYTES>>>(
        SELB_INX,  0, BSE, E, 2 * BSE,
        SELB_WEFF, 0, EE,  E, 2 * EE,
        nullptr, 0, 0, 0, E, 0,
        /*emode=*/2, E, 1.0f);

    // 4. transpose+split V -> Vt hi/lo
    transpose_v_kernel<<<dim3(S / 32, E / 32, BATCH), 256>>>();

    // 5. scores = Q @ K^T / 32 -> P hi/lo planes
    gemm_hmma<<<dim3(S / 128, S / 128, BATCH), NTHREADS, GEMM_SMEM_BYTES>>>(
        SELB_QK, 0,       BSE, E, SE,
        SELB_QK, 2 * BSE, BSE, E, SE,
        nullptr, SELB_P, 0, (long long)BATCH * SS, S, SS,
        /*emode=*/1, E, 1.0f / 32.0f);

    // 6. softmax rows (hi/lo in place)
    softmax_kernel<<<BATCH * S, 256>>>();

    // 7. attn_out = P @ Vt^T -> AO hi/lo planes
    gemm_hmma<<<dim3(E / 128, S / 128, BATCH), NTHREADS, GEMM_SMEM_BYTES>>>(
        SELB_P,  0, (long long)BATCH * SS, S, SS,
        SELB_VT, 0, BSE, S, SE,
        nullptr, SELB_AO, 0, BSE, E, SE,
        /*emode=*/1, S, 1.0f);

    // 8. final = attn_out @ O^T -> fp32 out
    gemm_hmma<<<dim3(E / 128, BS / 128, 1), NTHREADS, GEMM_SMEM_BYTES>>>(
        SELB_AO, 0, BSE, E, 0,
        SELB_OW, 0, EE,  E, 0,
        out, 0, 0, 0, E, 0,
        /*emode=*/0, E, 1.0f);
}

// round 14
// speedup vs baseline: 1.3329x; 1.3329x over previous
#include <cuda_runtime.h>
#include <cstdint>

#define E 1024
#define R 16
#define BATCH 4
#define S 2048
#define BS (BATCH * S)

// ---------------- device scratch ----------------
__device__ float g_Weff[3][(size_t)E * E];                 // 12 MB
__device__ float g_QKV[3][(size_t)BATCH * S * E];          // 96 MB
__device__ float g_Vt[(size_t)BATCH * S * E];              // 32 MB (V^T per batch: [E][S])
__device__ float g_scores[(size_t)BATCH * S * S];          // 64 MB
__device__ float g_attnout[(size_t)BATCH * S * E];         // 32 MB

#define SEL_EXT   0
#define SEL_WEFF  1
#define SEL_QKV   2
#define SEL_SCORE 3
#define SEL_AOUT  4
#define SEL_VT    5

__device__ __forceinline__ float* resolve_buf(int sel, const float* ext) {
    switch (sel) {
        case SEL_WEFF:  return &g_Weff[0][0];
        case SEL_QKV:   return &g_QKV[0][0];
        case SEL_SCORE: return &g_scores[0];
        case SEL_AOUT:  return &g_attnout[0];
        case SEL_VT:    return &g_Vt[0];
        default:        return (float*)ext;
    }
}

// ---------------- bf16 helpers ----------------
__device__ __forceinline__ uint32_t bf16x2_rn(float x0, float x1) {
    uint32_t r;
    asm("cvt.rn.bf16x2.f32 %0, %1, %2;" : "=r"(r) : "f"(x1), "f"(x0));
    return r;
}
__device__ __forceinline__ float bf_lo_f(uint32_t w) { return __uint_as_float(w << 16); }
__device__ __forceinline__ float bf_hi_f(uint32_t w) { return __uint_as_float(w & 0xffff0000u); }

__device__ __forceinline__ void mma_bf16(float* c, const uint32_t* a, const uint32_t* b) {
    asm volatile("mma.sync.aligned.m16n8k16.row.col.f32.bf16.bf16.f32 "
        "{%0,%1,%2,%3}, {%4,%5,%6,%7}, {%8,%9}, {%0,%1,%2,%3};"
        : "+f"(c[0]), "+f"(c[1]), "+f"(c[2]), "+f"(c[3])
        : "r"(a[0]), "r"(a[1]), "r"(a[2]), "r"(a[3]), "r"(b[0]), "r"(b[1]));
}

// ---------------- W_eff = W + B @ A ----------------
__global__ __launch_bounds__(256) void weff_kernel(
    const float* __restrict__ Wq, const float* __restrict__ Wk, const float* __restrict__ Wv,
    const float* __restrict__ Aq, const float* __restrict__ Bq,
    const float* __restrict__ Ak, const float* __restrict__ Bk,
    const float* __restrict__ Av, const float* __restrict__ Bv)
{
    const int z = blockIdx.z;
    const float* W  = (z == 0) ? Wq : (z == 1) ? Wk : Wv;
    const float* Am = (z == 0) ? Aq : (z == 1) ? Ak : Av;
    const float* Bm = (z == 0) ? Bq : (z == 1) ? Bk : Bv;
    const int idx = blockIdx.x * 256 + threadIdx.x;
    const int f = idx >> 10;
    const int e = idx & 1023;
    float sum = W[idx];
#pragma unroll
    for (int r = 0; r < R; r++)
        sum += Bm[f * R + r] * Am[r * E + e];
    g_Weff[z][idx] = sum;
}

// ---------------- V transpose: Vt[b][e][s] = V[b][s][e] ----------------
__global__ __launch_bounds__(256) void transpose_v_kernel()
{
    __shared__ float t[32][33];
    const int b = blockIdx.z;
    const int s0 = blockIdx.x * 32;
    const int e0 = blockIdx.y * 32;
    const int tx = threadIdx.x & 31;
    const int ty = threadIdx.x >> 5;   // 0..7
    const float* V = &g_QKV[2][0] + (long long)b * S * E;
    float* Vt = &g_Vt[0] + (long long)b * S * E;
#pragma unroll
    for (int r = 0; r < 4; r++)
        t[ty + r * 8][tx] = V[(long long)(s0 + ty + r * 8) * E + e0 + tx];
    __syncthreads();
#pragma unroll
    for (int r = 0; r < 4; r++)
        Vt[(long long)(e0 + ty + r * 8) * S + s0 + tx] = t[tx][ty + r * 8];
}

// ---------------- split-BF16 3-term HMMA GEMM (R9-proven fastest config) -------
// C[M,N] = alpha * A[M,K] @ B[N,K]^T (row-major). x -> bf16 hi + bf16 lo;
// acc += Ah*Bh + Al*Bh + Ah*Bl (Al*Bl dropped, ~2^-16 rel; fp32 TC accum).
// CTA 128x128x32, 8 warps (2x4), warp tile 64x32, 2 CTAs/SM.
// Producer (LDG / cvt+STS for step+1) interleaved with the two kc compute
// blocks of the current step:
//   ldg_half0; compute_kc0; sts_half0+ldg_half1; compute_kc1; sts_half1; sync
// Smem word layout per buffer (8192 words), proven since R7:
//  A hi 0..2047, A lo 2048..4095   (fb = (m>>4)*2 + kc, 128-word frag blocks)
//  B hi 4096..6143, B lo 6144..8191 (fb = (n>>3)*2 + kc, 64-word frag blocks)
// extA0/1/2: z-indexed external A inputs (merges the 3 QKV projections).
#define GEMM_SMEM_BYTES (2 * 8192 * 4)
#define NTHREADS 256

__global__ __launch_bounds__(NTHREADS, 2) void gemm_hmma(
    const float* extA0, const float* extA1, const float* extA2,
    int selA, long long offA, int ldA, long long sA,
    const float* extB, int selB, long long offB, int ldB, long long sB,
    float* extC, int selC, long long offC, int ldC, long long sC,
    int K, float alpha)
{
    extern __shared__ uint32_t smw[];
    const int tid = threadIdx.x;
    const int wid = tid >> 5, lane = tid & 31;
    const int g = lane >> 2, t4 = lane & 3;
    const int warp_m = wid & 1, warp_n = wid >> 1;   // 2x4 warps, 64x32 warp tile

    const float* extAz = (blockIdx.z == 0) ? extA0 : (blockIdx.z == 1) ? extA1 : extA2;
    const float* Ag = resolve_buf(selA, extAz) + offA + (long long)blockIdx.z * sA
                      + (long long)blockIdx.y * 128 * ldA;
    const float* Bg = resolve_buf(selB, extB) + offB + (long long)blockIdx.z * sB
                      + (long long)blockIdx.x * 128 * ldB;
    float* Cg = resolve_buf(selC, extC) + offC + (long long)blockIdx.z * sC;

    float acc[4][4][4];
#pragma unroll
    for (int i = 0; i < 4; i++)
#pragma unroll
        for (int j = 0; j < 4; j++)
#pragma unroll
            for (int q = 0; q < 4; q++) acc[i][j][q] = 0.f;

    float4 va[2], vb[2];   // producer regs: 2 j-slots live at a time

    auto ldg_half = [&](int step, int h) {
#pragma unroll
        for (int j = 0; j < 2; j++) {
            const int i = tid + (2 * h + j) * NTHREADS;   // 0..1023 float4 slots
            const int m = i >> 3, q = i & 7;
            va[j] = *reinterpret_cast<const float4*>(Ag + (long long)m * ldA + step * 32 + q * 4);
            vb[j] = *reinterpret_cast<const float4*>(Bg + (long long)m * ldB + step * 32 + q * 4);
        }
    };

    auto sts_half = [&](int s, int h) {
        uint32_t* base = smw + s * 8192;
#pragma unroll
        for (int j = 0; j < 2; j++) {
            const int i = tid + (2 * h + j) * NTHREADS;
            const int m = i >> 3, q = i & 7;
            const int kc = q >> 2;
            const int khalf = (q >> 1) & 1;
            const int tp = (q & 1) * 2;
            const float xs[4] = { va[j].x, va[j].y, va[j].z, va[j].w };
            const float ys[4] = { vb[j].x, vb[j].y, vb[j].z, vb[j].w };
            {
                const int fb = (m >> 4) * 2 + kc;
                const int reg = ((m >> 3) & 1) + 2 * khalf;
#pragma unroll
                for (int w = 0; w < 2; w++) {
                    const float x0 = xs[w * 2], x1 = xs[w * 2 + 1];
                    const uint32_t hh = bf16x2_rn(x0, x1);
                    const uint32_t ll = bf16x2_rn(x0 - bf_lo_f(hh), x1 - bf_hi_f(hh));
                    const int idx = fb * 128 + ((m & 7) * 4 + tp + w) * 4 + reg;
                    base[idx] = hh;
                    base[2048 + idx] = ll;
                }
            }
            {
                const int fb = (m >> 3) * 2 + kc;
#pragma unroll
                for (int w = 0; w < 2; w++) {
                    const float x0 = ys[w * 2], x1 = ys[w * 2 + 1];
                    const uint32_t hh = bf16x2_rn(x0, x1);
                    const uint32_t ll = bf16x2_rn(x0 - bf_lo_f(hh), x1 - bf_hi_f(hh));
                    const int idx = fb * 64 + ((m & 7) * 4 + tp + w) * 2 + khalf;
                    base[4096 + idx] = hh;
                    base[6144 + idx] = ll;
                }
            }
        }
    };

    auto compute_kc = [&](int s, int kc) {
        const uint32_t* base = smw + s * 8192;
        uint32_t aF[2][4][4];
#pragma unroll
        for (int mt = 0; mt < 4; mt++) {
            const int fb = (warp_m * 4 + mt) * 2 + kc;
            const uint4 h = *reinterpret_cast<const uint4*>(base + fb * 128 + lane * 4);
            const uint4 l = *reinterpret_cast<const uint4*>(base + 2048 + fb * 128 + lane * 4);
            aF[0][mt][0] = h.x; aF[0][mt][1] = h.y; aF[0][mt][2] = h.z; aF[0][mt][3] = h.w;
            aF[1][mt][0] = l.x; aF[1][mt][1] = l.y; aF[1][mt][2] = l.z; aF[1][mt][3] = l.w;
        }
#pragma unroll
        for (int nh = 0; nh < 2; nh++) {
            uint32_t bF[2][2][2];
#pragma unroll
            for (int nt = 0; nt < 2; nt++) {
                const int fb = (warp_n * 4 + nh * 2 + nt) * 2 + kc;
                const uint2 h = *reinterpret_cast<const uint2*>(base + 4096 + fb * 64 + lane * 2);
                const uint2 l = *reinterpret_cast<const uint2*>(base + 6144 + fb * 64 + lane * 2);
                bF[0][nt][0] = h.x; bF[0][nt][1] = h.y;
                bF[1][nt][0] = l.x; bF[1][nt][1] = l.y;
            }
            // term 1: Ah * Bh
#pragma unroll
            for (int mt = 0; mt < 4; mt++)
#pragma unroll
                for (int nt = 0; nt < 2; nt++)
                    mma_bf16(acc[mt][nh * 2 + nt], aF[0][mt], bF[0][nt]);
            // term 2: Al * Bh
#pragma unroll
            for (int mt = 0; mt < 4; mt++)
#pragma unroll
                for (int nt = 0; nt < 2; nt++)
                    mma_bf16(acc[mt][nh * 2 + nt], aF[1][mt], bF[0][nt]);
            // term 3: Ah * Bl   (Al*Bl dropped)
#pragma unroll
            for (int mt = 0; mt < 4; mt++)
#pragma unroll
                for (int nt = 0; nt < 2; nt++)
                    mma_bf16(acc[mt][nh * 2 + nt], aF[0][mt], bF[1][nt]);
        }
    };

    const int nsteps = K / 32;
    ldg_half(0, 0); sts_half(0, 0);
    ldg_half(0, 1); sts_half(0, 1);
    __syncthreads();

    for (int step = 0; step < nsteps; step++) {
        const int s = step & 1;
        const bool more = (step + 1 < nsteps);
        if (more) ldg_half(step + 1, 0);
        compute_kc(s, 0);
        if (more) { sts_half(1 - s, 0); ldg_half(step + 1, 1); }
        compute_kc(s, 1);
        if (more) sts_half(1 - s, 1);
        __syncthreads();
    }

    // epilogue: warp rows warp_m*64 .. +63, cols warp_n*32 .. +31
#pragma unroll
    for (int mt = 0; mt < 4; mt++) {
        const long long row = (long long)blockIdx.y * 128 + warp_m * 64 + mt * 16 + g;
        const long long col0 = (long long)blockIdx.x * 128 + warp_n * 32;
#pragma unroll
        for (int nt = 0; nt < 4; nt++) {
            const long long col = col0 + nt * 8 + t4 * 2;
            float2 v0 = make_float2(acc[mt][nt][0] * alpha, acc[mt][nt][1] * alpha);
            float2 v1 = make_float2(acc[mt][nt][2] * alpha, acc[mt][nt][3] * alpha);
            *reinterpret_cast<float2*>(Cg + row * ldC + col) = v0;
            *reinterpret_cast<float2*>(Cg + (row + 8) * ldC + col) = v1;
        }
    }
}

// ---------------- row softmax over S=2048 ----------------
__global__ __launch_bounds__(256) void softmax_kernel()
{
    const long long row = blockIdx.x;
    float* p = &g_scores[0] + row * (long long)S;
    const int t = threadIdx.x;

    float v[8];
    float m = -1e30f;
#pragma unroll
    for (int i = 0; i < 8; i++) {
        v[i] = p[t + i * 256];
        m = fmaxf(m, v[i]);
    }
    __shared__ float red[8];
#pragma unroll
    for (int o = 16; o; o >>= 1) m = fmaxf(m, __shfl_xor_sync(0xffffffffu, m, o));
    if ((t & 31) == 0) red[t >> 5] = m;
    __syncthreads();
    float mx = red[0];
#pragma unroll
    for (int w = 1; w < 8; w++) mx = fmaxf(mx, red[w]);

    float s = 0.f;
#pragma unroll
    for (int i = 0; i < 8; i++) {
        v[i] = __expf(v[i] - mx);
        s += v[i];
    }
#pragma unroll
    for (int o = 16; o; o >>= 1) s += __shfl_xor_sync(0xffffffffu, s, o);
    __syncthreads();
    if ((t & 31) == 0) red[t >> 5] = s;
    __syncthreads();
    float tot = 0.f;
#pragma unroll
    for (int w = 0; w < 8; w++) tot += red[w];
    const float inv = 1.0f / tot;
#pragma unroll
    for (int i = 0; i < 8; i++) p[t + i * 256] = v[i] * inv;
}

// ---------------- launch ----------------
extern "C" void kernel_launch(void* const* d_in, const int* in_sizes, int n_in,
                              void* d_out, int out_size)
{
    (void)in_sizes; (void)n_in; (void)out_size;
    const float* query = (const float*)d_in[0];
    const float* key   = (const float*)d_in[1];
    const float* value = (const float*)d_in[2];
    const float* Qw    = (const float*)d_in[3];
    const float* Kw    = (const float*)d_in[4];
    const float* Vw    = (const float*)d_in[5];
    const float* Qa    = (const float*)d_in[6];
    const float* Qb    = (const float*)d_in[7];
    const float* Ka    = (const float*)d_in[8];
    const float* Kb    = (const float*)d_in[9];
    const float* Va    = (const float*)d_in[10];
    const float* Vb    = (const float*)d_in[11];
    const float* Ow    = (const float*)d_in[12];
    float* out = (float*)d_out;

    static bool attr_done = false;
    if (!attr_done) {
        cudaFuncSetAttribute(gemm_hmma, cudaFuncAttributeMaxDynamicSharedMemorySize,
                             GEMM_SMEM_BYTES);
        attr_done = true;
    }

    const long long EE  = (long long)E * E;
    const long long BSE = (long long)BATCH * S * E;
    const long long SE  = (long long)S * E;
    const long long SS  = (long long)S * S;

    // 1. fold LoRA into weights
    weff_kernel<<<dim3(E * E / 256, 1, 3), 256>>>(Qw, Kw, Vw, Qa, Qb, Ka, Kb, Va, Vb);

    // 2. Q/K/V projections merged into ONE launch (z picks input + weight/output)
    gemm_hmma<<<dim3(E / 128, BS / 128, 3), NTHREADS, GEMM_SMEM_BYTES>>>(
        query, key, value, SEL_EXT, 0, E, 0,
        nullptr, SEL_WEFF, 0, E, EE,
        nullptr, SEL_QKV,  0, E, BSE,
        E, 1.0f);

    // 3. transpose V -> Vt[b][e][s]
    transpose_v_kernel<<<dim3(S / 32, E / 32, BATCH), 256>>>();

    // 4. scores = Q @ K^T / 32
    gemm_hmma<<<dim3(S / 128, S / 128, BATCH), NTHREADS, GEMM_SMEM_BYTES>>>(
        nullptr, nullptr, nullptr, SEL_QKV, 0, E, SE,
        nullptr, SEL_QKV,   BSE, E, SE,
        nullptr, SEL_SCORE, 0,   S, SS,
        E, 1.0f / 32.0f);

    // 5. softmax rows
    softmax_kernel<<<BATCH * S, 256>>>();

    // 6. attn_out = P @ Vt^T   (NT with Vt as [E,S] K-major)
    gemm_hmma<<<dim3(E / 128, S / 128, BATCH), NTHREADS, GEMM_SMEM_BYTES>>>(
        nullptr, nullptr, nullptr, SEL_SCORE, 0, S, SS,
        nullptr, SEL_VT,   0, S, SE,
        nullptr, SEL_AOUT, 0, E, SE,
        S, 1.0f);

    // 7. final = attn_out @ O^T
    gemm_hmma<<<dim3(E / 128, BS / 128, 1), NTHREADS, GEMM_SMEM_BYTES>>>(
        nullptr, nullptr, nullptr, SEL_AOUT, 0, E, 0,
        Ow,  SEL_EXT, 0, E, 0,
        out, SEL_EXT, 0, E, 0,
        E, 1.0f);
}

// round 15
// speedup vs baseline: 1.4018x; 1.0517x over previous
#include <cuda_runtime.h>
#include <cstdint>

#define E 1024
#define R 16
#define BATCH 4
#define S 2048
#define BS (BATCH * S)

// ---------------- device scratch ----------------
__device__ float g_Weff[3][(size_t)E * E];                 // 12 MB
__device__ float g_QKV[3][(size_t)BATCH * S * E];          // 96 MB
__device__ float g_Vt[(size_t)BATCH * S * E];              // 32 MB (V^T per batch: [E][S])
__device__ float g_scores[(size_t)BATCH * S * S];          // 64 MB
__device__ float g_attnout[(size_t)BATCH * S * E];         // 32 MB

#define SEL_EXT   0
#define SEL_WEFF  1
#define SEL_QKV   2
#define SEL_SCORE 3
#define SEL_AOUT  4
#define SEL_VT    5

__device__ __forceinline__ float* resolve_buf(int sel, const float* ext) {
    switch (sel) {
        case SEL_WEFF:  return &g_Weff[0][0];
        case SEL_QKV:   return &g_QKV[0][0];
        case SEL_SCORE: return &g_scores[0];
        case SEL_AOUT:  return &g_attnout[0];
        case SEL_VT:    return &g_Vt[0];
        default:        return (float*)ext;
    }
}

// ---------------- bf16 helpers ----------------
__device__ __forceinline__ uint32_t bf16x2_rn(float x0, float x1) {
    uint32_t r;
    asm("cvt.rn.bf16x2.f32 %0, %1, %2;" : "=r"(r) : "f"(x1), "f"(x0));
    return r;
}
__device__ __forceinline__ float bf_lo_f(uint32_t w) { return __uint_as_float(w << 16); }
__device__ __forceinline__ float bf_hi_f(uint32_t w) { return __uint_as_float(w & 0xffff0000u); }

__device__ __forceinline__ void mma_bf16(float* c, const uint32_t* a, const uint32_t* b) {
    asm volatile("mma.sync.aligned.m16n8k16.row.col.f32.bf16.bf16.f32 "
        "{%0,%1,%2,%3}, {%4,%5,%6,%7}, {%8,%9}, {%0,%1,%2,%3};"
        : "+f"(c[0]), "+f"(c[1]), "+f"(c[2]), "+f"(c[3])
        : "r"(a[0]), "r"(a[1]), "r"(a[2]), "r"(a[3]), "r"(b[0]), "r"(b[1]));
}

// ---------------- W_eff = W + B @ A ----------------
__global__ __launch_bounds__(256) void weff_kernel(
    const float* __restrict__ Wq, const float* __restrict__ Wk, const float* __restrict__ Wv,
    const float* __restrict__ Aq, const float* __restrict__ Bq,
    const float* __restrict__ Ak, const float* __restrict__ Bk,
    const float* __restrict__ Av, const float* __restrict__ Bv)
{
    const int z = blockIdx.z;
    const float* W  = (z == 0) ? Wq : (z == 1) ? Wk : Wv;
    const float* Am = (z == 0) ? Aq : (z == 1) ? Ak : Av;
    const float* Bm = (z == 0) ? Bq : (z == 1) ? Bk : Bv;
    const int idx = blockIdx.x * 256 + threadIdx.x;
    const int f = idx >> 10;
    const int e = idx & 1023;
    float sum = W[idx];
#pragma unroll
    for (int r = 0; r < R; r++)
        sum += Bm[f * R + r] * Am[r * E + e];
    g_Weff[z][idx] = sum;
}

// ---------------- V transpose: Vt[b][e][s] = V[b][s][e] ----------------
__global__ __launch_bounds__(256) void transpose_v_kernel()
{
    __shared__ float t[32][33];
    const int b = blockIdx.z;
    const int s0 = blockIdx.x * 32;
    const int e0 = blockIdx.y * 32;
    const int tx = threadIdx.x & 31;
    const int ty = threadIdx.x >> 5;   // 0..7
    const float* V = &g_QKV[2][0] + (long long)b * S * E;
    float* Vt = &g_Vt[0] + (long long)b * S * E;
#pragma unroll
    for (int r = 0; r < 4; r++)
        t[ty + r * 8][tx] = V[(long long)(s0 + ty + r * 8) * E + e0 + tx];
    __syncthreads();
#pragma unroll
    for (int r = 0; r < 4; r++)
        Vt[(long long)(e0 + ty + r * 8) * S + s0 + tx] = t[tx][ty + r * 8];
}

// ---------------- split-BF16 3-term HMMA GEMM (R14 + bank-padded smem) ---------
// C[M,N] = alpha * A[M,K] @ B[N,K]^T (row-major). x -> bf16 hi + bf16 lo;
// acc += Ah*Bh + Al*Bh + Ah*Bl (Al*Bl dropped, ~2^-16 rel; fp32 TC accum).
// CTA 128x128x32, 8 warps (2x4), warp tile 64x32, 2 CTAs/SM.
// Producer interleaved with the two kc compute blocks (R9/R14 schedule).
// NEW: fragment-block strides padded 128->132 (A) and 64->68 (B) words so
// kc-adjacent blocks land on rotated banks — producer STS conflicts drop
// 4-way -> 2-way (A) and 2-way -> ~1 (B). Consumer LDS alignment preserved
// (132*4 % 16 == 0, 68*4 % 8 == 0); LDS remains conflict-free.
// Word layout per buffer (8576 words):
//  A hi [0, 2112)      : fb = (m>>4)*2 + kc, stride 132
//  A lo [2112, 4224)
//  B hi [4224, 6400)   : fb = (n>>3)*2 + kc, stride 68
//  B lo [6400, 8576)
#define A_STRIDE 132
#define B_STRIDE 68
#define A_LO     2112
#define B_HI     4224
#define B_LO     6400
#define BUF_WORDS 8576
#define GEMM_SMEM_BYTES (2 * BUF_WORDS * 4)
#define NTHREADS 256

__global__ __launch_bounds__(NTHREADS, 2) void gemm_hmma(
    const float* extA0, const float* extA1, const float* extA2,
    int selA, long long offA, int ldA, long long sA,
    const float* extB, int selB, long long offB, int ldB, long long sB,
    float* extC, int selC, long long offC, int ldC, long long sC,
    int K, float alpha)
{
    extern __shared__ uint32_t smw[];
    const int tid = threadIdx.x;
    const int wid = tid >> 5, lane = tid & 31;
    const int g = lane >> 2, t4 = lane & 3;
    const int warp_m = wid & 1, warp_n = wid >> 1;   // 2x4 warps, 64x32 warp tile

    const float* extAz = (blockIdx.z == 0) ? extA0 : (blockIdx.z == 1) ? extA1 : extA2;
    const float* Ag = resolve_buf(selA, extAz) + offA + (long long)blockIdx.z * sA
                      + (long long)blockIdx.y * 128 * ldA;
    const float* Bg = resolve_buf(selB, extB) + offB + (long long)blockIdx.z * sB
                      + (long long)blockIdx.x * 128 * ldB;
    float* Cg = resolve_buf(selC, extC) + offC + (long long)blockIdx.z * sC;

    float acc[4][4][4];
#pragma unroll
    for (int i = 0; i < 4; i++)
#pragma unroll
        for (int j = 0; j < 4; j++)
#pragma unroll
            for (int q = 0; q < 4; q++) acc[i][j][q] = 0.f;

    float4 va[2], vb[2];   // producer regs: 2 j-slots live at a time

    auto ldg_half = [&](int step, int h) {
#pragma unroll
        for (int j = 0; j < 2; j++) {
            const int i = tid + (2 * h + j) * NTHREADS;   // 0..1023 float4 slots
            const int m = i >> 3, q = i & 7;
            va[j] = *reinterpret_cast<const float4*>(Ag + (long long)m * ldA + step * 32 + q * 4);
            vb[j] = *reinterpret_cast<const float4*>(Bg + (long long)m * ldB + step * 32 + q * 4);
        }
    };

    auto sts_half = [&](int s, int h) {
        uint32_t* base = smw + s * BUF_WORDS;
#pragma unroll
        for (int j = 0; j < 2; j++) {
            const int i = tid + (2 * h + j) * NTHREADS;
            const int m = i >> 3, q = i & 7;
            const int kc = q >> 2;
            const int khalf = (q >> 1) & 1;
            const int tp = (q & 1) * 2;
            const float xs[4] = { va[j].x, va[j].y, va[j].z, va[j].w };
            const float ys[4] = { vb[j].x, vb[j].y, vb[j].z, vb[j].w };
            {
                const int fb = (m >> 4) * 2 + kc;
                const int reg = ((m >> 3) & 1) + 2 * khalf;
#pragma unroll
                for (int w = 0; w < 2; w++) {
                    const float x0 = xs[w * 2], x1 = xs[w * 2 + 1];
                    const uint32_t hh = bf16x2_rn(x0, x1);
                    const uint32_t ll = bf16x2_rn(x0 - bf_lo_f(hh), x1 - bf_hi_f(hh));
                    const int idx = fb * A_STRIDE + ((m & 7) * 4 + tp + w) * 4 + reg;
                    base[idx] = hh;
                    base[A_LO + idx] = ll;
                }
            }
            {
                const int fb = (m >> 3) * 2 + kc;
#pragma unroll
                for (int w = 0; w < 2; w++) {
                    const float x0 = ys[w * 2], x1 = ys[w * 2 + 1];
                    const uint32_t hh = bf16x2_rn(x0, x1);
                    const uint32_t ll = bf16x2_rn(x0 - bf_lo_f(hh), x1 - bf_hi_f(hh));
                    const int idx = fb * B_STRIDE + ((m & 7) * 4 + tp + w) * 2 + khalf;
                    base[B_HI + idx] = hh;
                    base[B_LO + idx] = ll;
                }
            }
        }
    };

    auto compute_kc = [&](int s, int kc) {
        const uint32_t* base = smw + s * BUF_WORDS;
        uint32_t aF[2][4][4];
#pragma unroll
        for (int mt = 0; mt < 4; mt++) {
            const int fb = (warp_m * 4 + mt) * 2 + kc;
            const uint4 h = *reinterpret_cast<const uint4*>(base + fb * A_STRIDE + lane * 4);
            const uint4 l = *reinterpret_cast<const uint4*>(base + A_LO + fb * A_STRIDE + lane * 4);
            aF[0][mt][0] = h.x; aF[0][mt][1] = h.y; aF[0][mt][2] = h.z; aF[0][mt][3] = h.w;
            aF[1][mt][0] = l.x; aF[1][mt][1] = l.y; aF[1][mt][2] = l.z; aF[1][mt][3] = l.w;
        }
#pragma unroll
        for (int nh = 0; nh < 2; nh++) {
            uint32_t bF[2][2][2];
#pragma unroll
            for (int nt = 0; nt < 2; nt++) {
                const int fb = (warp_n * 4 + nh * 2 + nt) * 2 + kc;
                const uint2 h = *reinterpret_cast<const uint2*>(base + B_HI + fb * B_STRIDE + lane * 2);
                const uint2 l = *reinterpret_cast<const uint2*>(base + B_LO + fb * B_STRIDE + lane * 2);
                bF[0][nt][0] = h.x; bF[0][nt][1] = h.y;
                bF[1][nt][0] = l.x; bF[1][nt][1] = l.y;
            }
            // term 1: Ah * Bh
#pragma unroll
            for (int mt = 0; mt < 4; mt++)
#pragma unroll
                for (int nt = 0; nt < 2; nt++)
                    mma_bf16(acc[mt][nh * 2 + nt], aF[0][mt], bF[0][nt]);
            // term 2: Al * Bh
#pragma unroll
            for (int mt = 0; mt < 4; mt++)
#pragma unroll
                for (int nt = 0; nt < 2; nt++)
                    mma_bf16(acc[mt][nh * 2 + nt], aF[1][mt], bF[0][nt]);
            // term 3: Ah * Bl   (Al*Bl dropped)
#pragma unroll
            for (int mt = 0; mt < 4; mt++)
#pragma unroll
                for (int nt = 0; nt < 2; nt++)
                    mma_bf16(acc[mt][nh * 2 + nt], aF[0][mt], bF[1][nt]);
        }
    };

    const int nsteps = K / 32;
    ldg_half(0, 0); sts_half(0, 0);
    ldg_half(0, 1); sts_half(0, 1);
    __syncthreads();

    for (int step = 0; step < nsteps; step++) {
        const int s = step & 1;
        const bool more = (step + 1 < nsteps);
        if (more) ldg_half(step + 1, 0);
        compute_kc(s, 0);
        if (more) { sts_half(1 - s, 0); ldg_half(step + 1, 1); }
        compute_kc(s, 1);
        if (more) sts_half(1 - s, 1);
        __syncthreads();
    }

    // epilogue: warp rows warp_m*64 .. +63, cols warp_n*32 .. +31
#pragma unroll
    for (int mt = 0; mt < 4; mt++) {
        const long long row = (long long)blockIdx.y * 128 + warp_m * 64 + mt * 16 + g;
        const long long col0 = (long long)blockIdx.x * 128 + warp_n * 32;
#pragma unroll
        for (int nt = 0; nt < 4; nt++) {
            const long long col = col0 + nt * 8 + t4 * 2;
            float2 v0 = make_float2(acc[mt][nt][0] * alpha, acc[mt][nt][1] * alpha);
            float2 v1 = make_float2(acc[mt][nt][2] * alpha, acc[mt][nt][3] * alpha);
            *reinterpret_cast<float2*>(Cg + row * ldC + col) = v0;
            *reinterpret_cast<float2*>(Cg + (row + 8) * ldC + col) = v1;
        }
    }
}

// ---------------- row softmax over S=2048, float4-vectorized ----------------
__global__ __launch_bounds__(256) void softmax_kernel()
{
    const long long row = blockIdx.x;
    float4* p4 = reinterpret_cast<float4*>(&g_scores[0] + row * (long long)S);
    const int t = threadIdx.x;

    float4 v[2];
    float m = -1e30f;
#pragma unroll
    for (int i = 0; i < 2; i++) {
        v[i] = p4[t + i * 256];
        m = fmaxf(m, fmaxf(fmaxf(v[i].x, v[i].y), fmaxf(v[i].z, v[i].w)));
    }
    __shared__ float red[8];
#pragma unroll
    for (int o = 16; o; o >>= 1) m = fmaxf(m, __shfl_xor_sync(0xffffffffu, m, o));
    if ((t & 31) == 0) red[t >> 5] = m;
    __syncthreads();
    float mx = red[0];
#pragma unroll
    for (int w = 1; w < 8; w++) mx = fmaxf(mx, red[w]);

    float s = 0.f;
#pragma unroll
    for (int i = 0; i < 2; i++) {
        v[i].x = __expf(v[i].x - mx);
        v[i].y = __expf(v[i].y - mx);
        v[i].z = __expf(v[i].z - mx);
        v[i].w = __expf(v[i].w - mx);
        s += (v[i].x + v[i].y) + (v[i].z + v[i].w);
    }
#pragma unroll
    for (int o = 16; o; o >>= 1) s += __shfl_xor_sync(0xffffffffu, s, o);
    __syncthreads();
    if ((t & 31) == 0) red[t >> 5] = s;
    __syncthreads();
    float tot = 0.f;
#pragma unroll
    for (int w = 0; w < 8; w++) tot += red[w];
    const float inv = 1.0f / tot;
#pragma unroll
    for (int i = 0; i < 2; i++) {
        v[i].x *= inv; v[i].y *= inv; v[i].z *= inv; v[i].w *= inv;
        p4[t + i * 256] = v[i];
    }
}

// ---------------- launch ----------------
extern "C" void kernel_launch(void* const* d_in, const int* in_sizes, int n_in,
                              void* d_out, int out_size)
{
    (void)in_sizes; (void)n_in; (void)out_size;
    const float* query = (const float*)d_in[0];
    const float* key   = (const float*)d_in[1];
    const float* value = (const float*)d_in[2];
    const float* Qw    = (const float*)d_in[3];
    const float* Kw    = (const float*)d_in[4];
    const float* Vw    = (const float*)d_in[5];
    const float* Qa    = (const float*)d_in[6];
    const float* Qb    = (const float*)d_in[7];
    const float* Ka    = (const float*)d_in[8];
    const float* Kb    = (const float*)d_in[9];
    const float* Va    = (const float*)d_in[10];
    const float* Vb    = (const float*)d_in[11];
    const float* Ow    = (const float*)d_in[12];
    float* out = (float*)d_out;

    static bool attr_done = false;
    if (!attr_done) {
        cudaFuncSetAttribute(gemm_hmma, cudaFuncAttributeMaxDynamicSharedMemorySize,
                             GEMM_SMEM_BYTES);
        attr_done = true;
    }

    const long long EE  = (long long)E * E;
    const long long BSE = (long long)BATCH * S * E;
    const long long SE  = (long long)S * E;
    const long long SS  = (long long)S * S;

    // 1. fold LoRA into weights
    weff_kernel<<<dim3(E * E / 256, 1, 3), 256>>>(Qw, Kw, Vw, Qa, Qb, Ka, Kb, Va, Vb);

    // 2. Q/K/V projections merged into ONE launch (z picks input + weight/output)
    gemm_hmma<<<dim3(E / 128, BS / 128, 3), NTHREADS, GEMM_SMEM_BYTES>>>(
        query, key, value, SEL_EXT, 0, E, 0,
        nullptr, SEL_WEFF, 0, E, EE,
        nullptr, SEL_QKV,  0, E, BSE,
        E, 1.0f);

    // 3. transpose V -> Vt[b][e][s]
    transpose_v_kernel<<<dim3(S / 32, E / 32, BATCH), 256>>>();

    // 4. scores = Q @ K^T / 32
    gemm_hmma<<<dim3(S / 128, S / 128, BATCH), NTHREADS, GEMM_SMEM_BYTES>>>(
        nullptr, nullptr, nullptr, SEL_QKV, 0, E, SE,
        nullptr, SEL_QKV,   BSE, E, SE,
        nullptr, SEL_SCORE, 0,   S, SS,
        E, 1.0f / 32.0f);

    // 5. softmax rows
    softmax_kernel<<<BATCH * S, 256>>>();

    // 6. attn_out = P @ Vt^T   (NT with Vt as [E,S] K-major)
    gemm_hmma<<<dim3(E / 128, S / 128, BATCH), NTHREADS, GEMM_SMEM_BYTES>>>(
        nullptr, nullptr, nullptr, SEL_SCORE, 0, S, SS,
        nullptr, SEL_VT,   0, S, SE,
        nullptr, SEL_AOUT, 0, E, SE,
        S, 1.0f);

    // 7. final = attn_out @ O^T
    gemm_hmma<<<dim3(E / 128, BS / 128, 1), NTHREADS, GEMM_SMEM_BYTES>>>(
        nullptr, nullptr, nullptr, SEL_AOUT, 0, E, 0,
        Ow,  SEL_EXT, 0, E, 0,
        out, SEL_EXT, 0, E, 0,
        E, 1.0f);
}